// round 15
// baseline (speedup 1.0000x reference)
#include <cuda_runtime.h>
#include <cuda_bf16.h>
#include <math.h>

#define B_  2
#define S_  2048
#define E_  512
#define NH_ 4
#define DH_ 128
#define R_  (B_*S_)

// ------------------------- device scratch -------------------------
__device__ float g_xm  [R_*E_];
__device__ float g_zsil[R_*E_];
__device__ float g_xc  [R_*E_];
__device__ float g_q   [R_*E_];
__device__ float g_k   [R_*E_];
__device__ float g_v   [R_*E_];
__device__ float g_h   [R_*E_];
__device__ float g_hs  [R_*E_];
__device__ float g_Wt  [E_*4*E_];          // [o][tap*512+i]
__device__ float g_ig  [B_*NH_*S_];
__device__ float g_fg  [B_*NH_*S_];
__device__ float g_dkey[B_*NH_*S_];
__device__ float g_mrow[B_*NH_*S_];
__device__ float g_mexp[B_*NH_*S_];

// ------------------------- helpers -------------------------
__device__ __forceinline__ void mma16(float c[4], const unsigned a[4], const unsigned b[2]){
  asm volatile("mma.sync.aligned.m16n8k16.row.col.f32.bf16.bf16.f32 "
    "{%0,%1,%2,%3}, {%4,%5,%6,%7}, {%8,%9}, {%0,%1,%2,%3};"
    : "+f"(c[0]),"+f"(c[1]),"+f"(c[2]),"+f"(c[3])
    : "r"(a[0]),"r"(a[1]),"r"(a[2]),"r"(a[3]), "r"(b[0]),"r"(b[1]));
}
__device__ __forceinline__ void ldm4(unsigned r[4], unsigned a){
  asm volatile("ldmatrix.sync.aligned.m8n8.x4.shared.b16 {%0,%1,%2,%3}, [%4];"
    : "=r"(r[0]),"=r"(r[1]),"=r"(r[2]),"=r"(r[3]) : "r"(a));
}
__device__ __forceinline__ float silu(float x){ return x/(1.f+__expf(-x)); }
__device__ __forceinline__ unsigned pkb(__nv_bfloat16 lo, __nv_bfloat16 hi){
  return ((unsigned)__bfloat16_as_ushort(hi)<<16) | (unsigned)__bfloat16_as_ushort(lo);
}
// split float4 (4 consecutive k) into 2 hi words + 2 lo words (bf16x2)
__device__ __forceinline__ void spb4(unsigned hw[2], unsigned lw[2], float4 v){
  __nv_bfloat16 h0=__float2bfloat16_rn(v.x), h1=__float2bfloat16_rn(v.y),
                h2=__float2bfloat16_rn(v.z), h3=__float2bfloat16_rn(v.w);
  float l0=v.x-__bfloat162float(h0), l1=v.y-__bfloat162float(h1),
        l2=v.z-__bfloat162float(h2), l3=v.w-__bfloat162float(h3);
  hw[0]=pkb(h0,h1); hw[1]=pkb(h2,h3);
  lw[0]=pkb(__float2bfloat16_rn(l0),__float2bfloat16_rn(l1));
  lw[1]=pkb(__float2bfloat16_rn(l2),__float2bfloat16_rn(l3));
}

// ---------------- conv weight repack: Wt[o][tap*512+i] ----------------
__global__ void k_wt(const float* __restrict__ conv_w){
  int o = blockIdx.x; int i = threadIdx.x;
  #pragma unroll
  for (int tap=0;tap<4;tap++)
    g_Wt[(size_t)o*2048 + tap*512 + i] = conv_w[((size_t)o*512+i)*4 + tap];
}

// ---------------- pipelined split-BF16 mma GEMM core (ldmatrix) ----------
#define WPR 12                   // 32-bit words per tile row (16 bf16 + pad)
#define TW  (128*WPR)            // words per tile
#define GST (4*TW)               // Ah,Al,Bh,Bl per stage
#define GEMM_SMEM (2*GST*4)      // 49152 bytes

__device__ __forceinline__ void mm_slice_bf(
    unsigned uAh, unsigned uAl, unsigned uBh, unsigned uBl,
    int wm, int wn, int lane, float acc[2][8][4])
{
  const int ar = ((lane>>3)&1)*8 + (lane&7);
  const int aw = (lane>>4)*4;
  const int br = (lane>>4)*8 + (lane&7);
  const int bw = ((lane>>3)&1)*4;
  unsigned ua[2][4], la[2][4];
  #pragma unroll
  for (int mt=0;mt<2;mt++){
    unsigned off = (unsigned)(((wm+mt*16+ar)*WPR + aw)*4);
    ldm4(ua[mt], uAh + off);
    ldm4(la[mt], uAl + off);
  }
  #pragma unroll
  for (int p=0;p<4;p++){
    unsigned off = (unsigned)(((wn + p*16 + br)*WPR + bw)*4);
    unsigned ub[4], lb[4];
    ldm4(ub, uBh + off);
    ldm4(lb, uBl + off);
    #pragma unroll
    for (int q=0;q<2;q++){
      unsigned ubq[2]={ub[2*q],ub[2*q+1]}, lbq[2]={lb[2*q],lb[2*q+1]};
      int nt = 2*p+q;
      #pragma unroll
      for (int mt=0;mt<2;mt++){
        mma16(acc[mt][nt], la[mt], ubq);
        mma16(acc[mt][nt], ua[mt], lbq);
        mma16(acc[mt][nt], ua[mt], ubq);
      }
    }
  }
}

__device__ __forceinline__ void mm_core_bf(
    const float* __restrict__ A, int lda,
    const float* __restrict__ W, int ldw, int K,
    unsigned* __restrict__ smw, float acc[2][8][4])
{
  const int tid=threadIdx.x, warp=tid>>5, lane=tid&31;
  const int wm=(warp>>1)*32, wn=(warp&1)*64;
  const int m0=tid>>2, m1=m0+64, c0=(tid&3)*4, w0=c0>>1;
  const unsigned ubase = (unsigned)__cvta_generic_to_shared(smw);
  float4 ra0 = *(const float4*)&A[(size_t)m0*lda + c0];
  float4 ra1 = *(const float4*)&A[(size_t)m1*lda + c0];
  float4 rb0 = *(const float4*)&W[(size_t)m0*ldw + c0];
  float4 rb1 = *(const float4*)&W[(size_t)m1*ldw + c0];
  int buf = 0;
  for (int k0=0;k0<K;k0+=16){
    unsigned* Ah = smw + buf*GST;
    unsigned* Al = Ah + TW;
    unsigned* Bh = Al + TW;
    unsigned* Bl = Bh + TW;
    unsigned hw[2], lw[2];
    spb4(hw,lw,ra0); Ah[m0*WPR+w0]=hw[0]; Ah[m0*WPR+w0+1]=hw[1]; Al[m0*WPR+w0]=lw[0]; Al[m0*WPR+w0+1]=lw[1];
    spb4(hw,lw,ra1); Ah[m1*WPR+w0]=hw[0]; Ah[m1*WPR+w0+1]=hw[1]; Al[m1*WPR+w0]=lw[0]; Al[m1*WPR+w0+1]=lw[1];
    spb4(hw,lw,rb0); Bh[m0*WPR+w0]=hw[0]; Bh[m0*WPR+w0+1]=hw[1]; Bl[m0*WPR+w0]=lw[0]; Bl[m0*WPR+w0+1]=lw[1];
    spb4(hw,lw,rb1); Bh[m1*WPR+w0]=hw[0]; Bh[m1*WPR+w0+1]=hw[1]; Bl[m1*WPR+w0]=lw[0]; Bl[m1*WPR+w0+1]=lw[1];
    __syncthreads();
    if (k0+16 < K){
      ra0 = *(const float4*)&A[(size_t)m0*lda + k0+16 + c0];
      ra1 = *(const float4*)&A[(size_t)m1*lda + k0+16 + c0];
      rb0 = *(const float4*)&W[(size_t)m0*ldw + k0+16 + c0];
      rb1 = *(const float4*)&W[(size_t)m1*ldw + k0+16 + c0];
    }
    unsigned ust = ubase + (unsigned)(buf*GST*4);
    mm_slice_bf(ust, ust+TW*4, ust+2*TW*4, ust+3*TW*4, wm, wn, lane, acc);
    buf ^= 1;
  }
}

#define EPI_COORDS \
  const int tid=threadIdx.x, warp=tid>>5, lane=tid&31, gid=lane>>2, tig=lane&3; \
  const int wm=(warp>>1)*32, wn=(warp&1)*64; (void)wm; (void)tid;

// ---------------- up projection ----------------
__global__ __launch_bounds__(256,2) void k_up(const float* __restrict__ X,
                                              const float* __restrict__ Wup){
  extern __shared__ unsigned smw[];
  int bm = blockIdx.y*128, bn = blockIdx.x*128;
  float acc[2][8][4];
  #pragma unroll
  for(int i=0;i<2;i++)for(int j=0;j<8;j++)for(int e=0;e<4;e++)acc[i][j][e]=0;
  mm_core_bf(X+(size_t)bm*512, 512, Wup+(size_t)bn*512, 512, 512, smw, acc);
  EPI_COORDS;
  bool is_z = (bn >= 512);
  #pragma unroll
  for (int mt=0;mt<2;mt++){
    #pragma unroll
    for (int nt=0;nt<8;nt++){
      int row = bm+wm+mt*16+gid;
      int col = bn+wn+nt*8+tig*2;
      float* c = acc[mt][nt];
      if (!is_z){
        *(float2*)&g_xm[(size_t)row*512+col]     = make_float2(c[0],c[1]);
        *(float2*)&g_xm[(size_t)(row+8)*512+col] = make_float2(c[2],c[3]);
      } else {
        int cz = col-512;
        *(float2*)&g_zsil[(size_t)row*512+cz]     = make_float2(silu(c[0]),silu(c[1]));
        *(float2*)&g_zsil[(size_t)(row+8)*512+cz] = make_float2(silu(c[2]),silu(c[3]));
      }
    }
  }
}

// ---------------- causal conv1d as shifted GEMM + silu ----------------
__global__ __launch_bounds__(256,2) void k_conv(const float* __restrict__ convb){
  extern __shared__ unsigned smw[];
  int bm = blockIdx.y*128, bn = blockIdx.x*128;
  const int tid=threadIdx.x, warp=tid>>5, lane=tid&31, gid=lane>>2, tig=lane&3;
  const int wm=(warp>>1)*32, wn=(warp&1)*64;
  const int m0=tid>>2, m1=m0+64, c0=(tid&3)*4, w0=c0>>1;
  const int s0 = (bm+m0)&(S_-1), s1 = (bm+m1)&(S_-1);
  const unsigned ubase = (unsigned)__cvta_generic_to_shared(smw);
  float acc[2][8][4];
  #pragma unroll
  for(int i=0;i<2;i++)for(int j=0;j<8;j++)for(int e=0;e<4;e++)acc[i][j][e]=0;
  const float* W = g_Wt + (size_t)bn*2048;
  float4 ra0 = (s0-3>=0) ? *(const float4*)&g_xm[(size_t)(bm+m0-3)*512 + c0] : make_float4(0,0,0,0);
  float4 ra1 = (s1-3>=0) ? *(const float4*)&g_xm[(size_t)(bm+m1-3)*512 + c0] : make_float4(0,0,0,0);
  float4 rb0 = *(const float4*)&W[(size_t)m0*2048 + c0];
  float4 rb1 = *(const float4*)&W[(size_t)m1*2048 + c0];
  int buf = 0;
  for (int k0=0;k0<2048;k0+=16){
    unsigned* Ah = smw + buf*GST;
    unsigned* Al = Ah + TW;
    unsigned* Bh = Al + TW;
    unsigned* Bl = Bh + TW;
    unsigned hw[2], lw[2];
    spb4(hw,lw,ra0); Ah[m0*WPR+w0]=hw[0]; Ah[m0*WPR+w0+1]=hw[1]; Al[m0*WPR+w0]=lw[0]; Al[m0*WPR+w0+1]=lw[1];
    spb4(hw,lw,ra1); Ah[m1*WPR+w0]=hw[0]; Ah[m1*WPR+w0+1]=hw[1]; Al[m1*WPR+w0]=lw[0]; Al[m1*WPR+w0+1]=lw[1];
    spb4(hw,lw,rb0); Bh[m0*WPR+w0]=hw[0]; Bh[m0*WPR+w0+1]=hw[1]; Bl[m0*WPR+w0]=lw[0]; Bl[m0*WPR+w0+1]=lw[1];
    spb4(hw,lw,rb1); Bh[m1*WPR+w0]=hw[0]; Bh[m1*WPR+w0+1]=hw[1]; Bl[m1*WPR+w0]=lw[0]; Bl[m1*WPR+w0+1]=lw[1];
    __syncthreads();
    int kn = k0+16;
    if (kn < 2048){
      int tap = kn>>9, i0 = kn&511;
      ra0 = (s0+tap-3>=0) ? *(const float4*)&g_xm[(size_t)(bm+m0+tap-3)*512 + i0 + c0]
                          : make_float4(0,0,0,0);
      ra1 = (s1+tap-3>=0) ? *(const float4*)&g_xm[(size_t)(bm+m1+tap-3)*512 + i0 + c0]
                          : make_float4(0,0,0,0);
      rb0 = *(const float4*)&W[(size_t)m0*2048 + kn + c0];
      rb1 = *(const float4*)&W[(size_t)m1*2048 + kn + c0];
    }
    unsigned ust = ubase + (unsigned)(buf*GST*4);
    mm_slice_bf(ust, ust+TW*4, ust+2*TW*4, ust+3*TW*4, wm, wn, lane, acc);
    buf ^= 1;
  }
  #pragma unroll
  for (int mt=0;mt<2;mt++){
    #pragma unroll
    for (int nt=0;nt<8;nt++){
      int row = bm+wm+mt*16+gid;
      int col = bn+wn+nt*8+tig*2;
      float b0 = convb[col], b1 = convb[col+1];
      float* c = acc[mt][nt];
      *(float2*)&g_xc[(size_t)row*512+col]     = make_float2(silu(c[0]+b0),silu(c[1]+b1));
      *(float2*)&g_xc[(size_t)(row+8)*512+col] = make_float2(silu(c[2]+b0),silu(c[3]+b1));
    }
  }
}

// ---------------- headwise q/k/v ----------------
__global__ __launch_bounds__(256,2) void k_qkv(const float* __restrict__ Wq,
                                               const float* __restrict__ Wk,
                                               const float* __restrict__ Wv){
  extern __shared__ unsigned smw[];
  int zz = blockIdx.z; int op = zz>>2; int h = zz&3;
  const float* A  = (op==2 ? g_xm : g_xc) + h*128;
  const float* Wp = (op==0 ? Wq : (op==1 ? Wk : Wv)) + (size_t)h*128*128;
  float* Cp = (op==0 ? g_q : (op==1 ? g_k : g_v)) + h*128;
  int bm = blockIdx.y*128;
  float acc[2][8][4];
  #pragma unroll
  for(int i=0;i<2;i++)for(int j=0;j<8;j++)for(int e=0;e<4;e++)acc[i][j][e]=0;
  mm_core_bf(A+(size_t)bm*512, 512, Wp, 128, 128, smw, acc);
  EPI_COORDS;
  #pragma unroll
  for (int mt=0;mt<2;mt++){
    #pragma unroll
    for (int nt=0;nt<8;nt++){
      int row = bm+wm+mt*16+gid;
      int col = wn+nt*8+tig*2;
      float* c = acc[mt][nt];
      *(float2*)&Cp[(size_t)row*512+col]     = make_float2(c[0],c[1]);
      *(float2*)&Cp[(size_t)(row+8)*512+col] = make_float2(c[2],c[3]);
    }
  }
}

// ---------------- down projection + bias ----------------
__global__ __launch_bounds__(256,2) void k_down(const float* __restrict__ Wd,
                                                const float* __restrict__ bd,
                                                float* __restrict__ out){
  extern __shared__ unsigned smw[];
  int bm = blockIdx.y*128, bn = blockIdx.x*128;
  float acc[2][8][4];
  #pragma unroll
  for(int i=0;i<2;i++)for(int j=0;j<8;j++)for(int e=0;e<4;e++)acc[i][j][e]=0;
  mm_core_bf(g_hs+(size_t)bm*512, 512, Wd+(size_t)bn*512, 512, 512, smw, acc);
  EPI_COORDS;
  #pragma unroll
  for (int mt=0;mt<2;mt++){
    #pragma unroll
    for (int nt=0;nt<8;nt++){
      int row = bm+wm+mt*16+gid;
      int col = bn+wn+nt*8+tig*2;
      float b0 = bd[col], b1 = bd[col+1];
      float* c = acc[mt][nt];
      *(float2*)&out[(size_t)row*512+col]     = make_float2(c[0]+b0,c[1]+b1);
      *(float2*)&out[(size_t)(row+8)*512+col] = make_float2(c[2]+b0,c[3]+b1);
    }
  }
}

// ---------------- gate projections ----------------
__global__ void k_gates(const float* __restrict__ Wi, const float* __restrict__ bi,
                        const float* __restrict__ Wf, const float* __restrict__ bf){
  int r = blockIdx.x; int tid = threadIdx.x;
  float pi[4]={0,0,0,0}, pf[4]={0,0,0,0};
  const float* qr = g_q + (size_t)r*512;
  const float* kr = g_k + (size_t)r*512;
  const float* vr = g_v + (size_t)r*512;
  for (int e=tid; e<512; e+=128){
    float a=qr[e], c=kr[e], d=vr[e];
    #pragma unroll
    for (int h=0;h<4;h++){
      const float* wih = Wi + h*1536; const float* wfh = Wf + h*1536;
      pi[h] += a*wih[e] + c*wih[512+e] + d*wih[1024+e];
      pf[h] += a*wfh[e] + c*wfh[512+e] + d*wfh[1024+e];
    }
  }
  __shared__ float red[8][128];
  #pragma unroll
  for (int h=0;h<4;h++){ red[h][tid]=pi[h]; red[4+h][tid]=pf[h]; }
  __syncthreads();
  for (int sft=64; sft>=1; sft>>=1){
    if (tid < sft){
      #pragma unroll
      for (int a=0;a<8;a++) red[a][tid]+=red[a][tid+sft];
    }
    __syncthreads();
  }
  if (tid < 4){
    int b = r>>11, s = r&2047;
    g_ig[((size_t)b*4+tid)*2048 + s] = red[tid][0]   + bi[tid];
    g_fg[((size_t)b*4+tid)*2048 + s] = red[4+tid][0] + bf[tid];
  }
}

// ---------------- per-(b,h) scan ----------------
__global__ void k_scan(){
  int bh = blockIdx.x; int t = threadIdx.x;
  const float* fg = g_fg + (size_t)bh*2048;
  const float* ig = g_ig + (size_t)bh*2048;
  double lcum[8]; double run = 0.0;
  #pragma unroll
  for (int u=0;u<8;u++){
    double x = (double)fg[t*8+u];
    double ls = (x < 0.0) ? (x - log1p(exp(x))) : (-log1p(exp(-x)));
    run += ls; lcum[u] = run;
  }
  __shared__ double sh[256];
  sh[t] = run; __syncthreads();
  for (int off=1; off<256; off<<=1){
    double cur = sh[t]; double oth = (t>=off)? sh[t-off] : 0.0;
    __syncthreads(); sh[t] = cur + oth; __syncthreads();
  }
  double base = (t>0)? sh[t-1] : 0.0;
  double dv[8], lf[8]; double runm = -1e300;
  #pragma unroll
  for (int u=0;u<8;u++){
    double lfc = base + lcum[u];
    lf[u] = lfc; dv[u] = (double)ig[t*8+u] - lfc;
    if (dv[u] > runm) runm = dv[u];
  }
  __syncthreads();
  sh[t] = runm; __syncthreads();
  for (int off=1; off<256; off<<=1){
    double cur = sh[t]; double oth = (t>=off)? sh[t-off] : -1e300;
    __syncthreads(); sh[t] = (cur>oth)?cur:oth; __syncthreads();
  }
  double basem = (t>0)? sh[t-1] : -1e300;
  double rm = basem;
  #pragma unroll
  for (int u=0;u<8;u++){
    if (dv[u] > rm) rm = dv[u];
    int j = bh*2048 + t*8 + u;
    g_dkey[j] = (float)dv[u];
    g_mrow[j] = (float)rm;
    g_mexp[j] = (float)exp(-(lf[u] + rm));
  }
}

// ---------------- split-BF16 flash causal mLSTM attention (ldmatrix) -----
#define WQROW 68
#define WSROW 36
#define WQH   0
#define WQL   (WQH + 64*WQROW)
#define WBUF  (WQL + 64*WQROW)
#define WBUFSZ (2*128*WSROW)
#define WSSH  (WBUF + WBUFSZ)
#define WSSL  (WSSH + 64*WSROW)
#define WDK   (WSSL + 64*WSROW)
#define WRED  (WDK + 64)
#define WSINV (WRED + 128)
#define ATT_WORDS (WSINV + 64)
#define ATT_SMEM (ATT_WORDS*4)

__global__ __launch_bounds__(256,2) void k_attn(){
  extern __shared__ unsigned smu[];
  unsigned* QH = smu + WQH;
  unsigned* QL = smu + WQL;
  unsigned* KH = smu + WBUF;               // [64][68]
  unsigned* KL = KH + 64*WQROW;
  unsigned* VtH = smu + WBUF;              // [128][36] (aliases K region)
  unsigned* VtL = VtH + 128*WSROW;
  unsigned* SSH = smu + WSSH;              // [64][36]
  unsigned* SSL = smu + WSSL;
  float* dks = (float*)(smu + WDK);
  float* red = (float*)(smu + WRED);
  float* sinv= (float*)(smu + WSINV);
  const unsigned ub0 = (unsigned)__cvta_generic_to_shared(smu);
  const unsigned uQH = ub0 + WQH*4,  uQL = ub0 + WQL*4;
  const unsigned uKH = ub0 + WBUF*4, uKL = uKH + 64*WQROW*4;
  const unsigned uVtH= ub0 + WBUF*4, uVtL= uVtH + 128*WSROW*4;
  const unsigned uSSH= ub0 + WSSH*4, uSSL= ub0 + WSSL*4;

  int bh = blockIdx.y; int b = bh>>2, h = bh&3;
  int it = (int)gridDim.x - 1 - (int)blockIdx.x;
  int i0 = it*64;
  const int tid=threadIdx.x, warp=tid>>5, lane=tid&31, gid=lane>>2, tig=lane&3;
  const int wr=warp>>1, wc=warp&1;
  const int qm = wr*16;
  const float scale = 0.08838834764831845f;
  const int lrow = tid>>5, lc4 = (tid&31)*4, lw0 = (tid&31)*2;
  const int jp = tid&31, db = (tid>>5)*16;
  const int ar = ((lane>>3)&1)*8 + (lane&7);
  const int aw = (lane>>4)*4;
  const int br = (lane>>4)*8 + (lane&7);
  const int bw = ((lane>>3)&1)*4;

  const float* qbase = g_q + ((size_t)(b*2048 + i0))*512 + h*128;
  #pragma unroll
  for (int u=0;u<8;u++){
    int row = lrow + u*8;
    unsigned hw[2], lw[2];
    spb4(hw,lw, *(const float4*)&qbase[(size_t)row*512 + lc4]);
    QH[row*WQROW + lw0] = hw[0]; QH[row*WQROW + lw0+1] = hw[1];
    QL[row*WQROW + lw0] = lw[0]; QL[row*WQROW + lw0+1] = lw[1];
  }
  float mr0 = g_mrow[bh*2048 + i0 + qm + gid];
  float mr1 = g_mrow[bh*2048 + i0 + qm + gid + 8];

  float oacc[8][4];
  #pragma unroll
  for (int nt=0;nt<8;nt++){oacc[nt][0]=0;oacc[nt][1]=0;oacc[nt][2]=0;oacc[nt][3]=0;}
  float psum0 = 0.f, psum1 = 0.f;

  float4 kreg[8], vreg[8];
  {
    const float* kb = g_k + ((size_t)(b*2048))*512 + h*128;
    #pragma unroll
    for (int u=0;u<8;u++){
      int row = lrow + u*8;
      kreg[u] = *(const float4*)&kb[(size_t)row*512 + lc4];
    }
  }

  for (int j0 = 0; j0 <= i0; j0 += 64){
    __syncthreads();
    #pragma unroll
    for (int u=0;u<8;u++){
      int row = lrow + u*8;
      unsigned hw[2], lw[2];
      spb4(hw,lw, kreg[u]);
      KH[row*WQROW + lw0] = hw[0]; KH[row*WQROW + lw0+1] = hw[1];
      KL[row*WQROW + lw0] = lw[0]; KL[row*WQROW + lw0+1] = lw[1];
    }
    if (tid < 64) dks[tid] = g_dkey[bh*2048 + j0 + tid];
    __syncthreads();

    // prefetch V (j-pair layout)
    {
      const float* vb = g_v + ((size_t)(b*2048 + j0))*512 + h*128;
      #pragma unroll
      for (int u=0;u<4;u++){
        vreg[u]   = *(const float4*)&vb[(size_t)(2*jp  )*512 + db + u*4];
        vreg[u+4] = *(const float4*)&vb[(size_t)(2*jp+1)*512 + db + u*4];
      }
    }

    // QK^T (ldmatrix): rows qm..qm+15, key cols wc*32..+31
    float sacc[4][4];
    #pragma unroll
    for (int nt=0;nt<4;nt++){sacc[nt][0]=0;sacc[nt][1]=0;sacc[nt][2]=0;sacc[nt][3]=0;}
    #pragma unroll
    for (int kk=0;kk<128;kk+=16){
      int wb = kk>>1;
      unsigned offA = (unsigned)(((qm+ar)*WQROW + wb + aw)*4);
      unsigned ua[4], la[4];
      ldm4(ua, uQH + offA);
      ldm4(la, uQL + offA);
      #pragma unroll
      for (int p=0;p<2;p++){
        unsigned offB = (unsigned)(((wc*32 + p*16 + br)*WQROW + wb + bw)*4);
        unsigned kb2[4], klb[4];
        ldm4(kb2, uKH + offB);
        ldm4(klb, uKL + offB);
        #pragma unroll
        for (int q=0;q<2;q++){
          unsigned ubq[2]={kb2[2*q],kb2[2*q+1]}, lbq[2]={klb[2*q],klb[2*q+1]};
          int nt = 2*p+q;
          mma16(sacc[nt], la, ubq);
          mma16(sacc[nt], ua, lbq);
          mma16(sacc[nt], ua, ubq);
        }
      }
    }
    bool diag = (j0 == i0);
    #pragma unroll
    for (int nt=0;nt<4;nt++){
      int jl = wc*32+nt*8+tig*2;
      float d0 = dks[jl], d1 = dks[jl+1];
      int il0 = qm+gid, il1 = il0+8;
      float s00 = sacc[nt][0]*scale*__expf(d0 - mr0);
      float s01 = sacc[nt][1]*scale*__expf(d1 - mr0);
      float s10 = sacc[nt][2]*scale*__expf(d0 - mr1);
      float s11 = sacc[nt][3]*scale*__expf(d1 - mr1);
      if (diag){
        if (jl   > il0) s00 = 0.f;
        if (jl+1 > il0) s01 = 0.f;
        if (jl   > il1) s10 = 0.f;
        if (jl+1 > il1) s11 = 0.f;
      }
      psum0 += s00 + s01;
      psum1 += s10 + s11;
      int jw = jl>>1;
      __nv_bfloat16 h00=__float2bfloat16_rn(s00), h01=__float2bfloat16_rn(s01),
                    h10=__float2bfloat16_rn(s10), h11=__float2bfloat16_rn(s11);
      SSH[il0*WSROW + jw] = pkb(h00,h01);
      SSH[il1*WSROW + jw] = pkb(h10,h11);
      SSL[il0*WSROW + jw] = pkb(__float2bfloat16_rn(s00-__bfloat162float(h00)),
                                __float2bfloat16_rn(s01-__bfloat162float(h01)));
      SSL[il1*WSROW + jw] = pkb(__float2bfloat16_rn(s10-__bfloat162float(h10)),
                                __float2bfloat16_rn(s11-__bfloat162float(h11)));
    }
    __syncthreads();                 // K consumed, S ready

    // store V transposed, j-pairs packed per word
    #pragma unroll
    for (int u=0;u<4;u++){
      const float* f0 = (const float*)&vreg[u];
      const float* f1 = (const float*)&vreg[u+4];
      #pragma unroll
      for (int cix=0;cix<4;cix++){
        int d = db + u*4 + cix;
        __nv_bfloat16 ha=__float2bfloat16_rn(f0[cix]), hb=__float2bfloat16_rn(f1[cix]);
        VtH[d*WSROW + jp] = pkb(ha,hb);
        VtL[d*WSROW + jp] = pkb(__float2bfloat16_rn(f0[cix]-__bfloat162float(ha)),
                                __float2bfloat16_rn(f1[cix]-__bfloat162float(hb)));
      }
    }
    __syncthreads();

    // prefetch next K tile
    if (j0 + 64 <= i0){
      const float* kb = g_k + ((size_t)(b*2048 + j0 + 64))*512 + h*128;
      #pragma unroll
      for (int u=0;u<8;u++){
        int row = lrow + u*8;
        kreg[u] = *(const float4*)&kb[(size_t)row*512 + lc4];
      }
    }

    // S @ V (ldmatrix): rows qm..qm+15, d cols wc*64..+63
    #pragma unroll
    for (int kk=0;kk<64;kk+=16){
      int wb = kk>>1;
      unsigned offA = (unsigned)(((qm+ar)*WSROW + wb + aw)*4);
      unsigned ua[4], la[4];
      ldm4(ua, uSSH + offA);
      ldm4(la, uSSL + offA);
      #pragma unroll
      for (int p=0;p<4;p++){
        unsigned offB = (unsigned)(((wc*64 + p*16 + br)*WSROW + wb + bw)*4);
        unsigned vb2[4], vlb[4];
        ldm4(vb2, uVtH + offB);
        ldm4(vlb, uVtL + offB);
        #pragma unroll
        for (int q=0;q<2;q++){
          unsigned ubq[2]={vb2[2*q],vb2[2*q+1]}, lbq[2]={vlb[2*q],vlb[2*q+1]};
          int nt = 2*p+q;
          mma16(oacc[nt], la, ubq);
          mma16(oacc[nt], ua, lbq);
          mma16(oacc[nt], ua, ubq);
        }
      }
    }
  }

  psum0 += __shfl_xor_sync(0xffffffffu, psum0, 1);
  psum0 += __shfl_xor_sync(0xffffffffu, psum0, 2);
  psum1 += __shfl_xor_sync(0xffffffffu, psum1, 1);
  psum1 += __shfl_xor_sync(0xffffffffu, psum1, 2);
  if (tig == 0){
    red[(qm+gid)*2   + wc] = psum0;
    red[(qm+gid+8)*2 + wc] = psum1;
  }
  __syncthreads();
  if (tid < 64){
    float s2 = red[tid*2] + red[tid*2+1];
    float nrm = fmaxf(fabsf(s2), g_mexp[bh*2048 + i0 + tid]);
    sinv[tid] = 1.f/(nrm + 1e-6f);
  }
  __syncthreads();

  float iv0 = sinv[qm+gid], iv1 = sinv[qm+gid+8];
  float* obase = g_h + ((size_t)(b*2048 + i0))*512 + h*128;
  #pragma unroll
  for (int nt=0;nt<8;nt++){
    int col = wc*64+nt*8+tig*2;
    *(float2*)&obase[(size_t)(qm+gid)*512 + col] =
      make_float2(oacc[nt][0]*iv0, oacc[nt][1]*iv0);
    *(float2*)&obase[(size_t)(qm+gid+8)*512 + col] =
      make_float2(oacc[nt][2]*iv1, oacc[nt][3]*iv1);
  }
}

// ---------------- groupnorm + skip + z-gate ----------------
__global__ void k_norm(const float* __restrict__ skip){
  int r = blockIdx.x; int t = threadIdx.x;
  float v[4];
  #pragma unroll
  for (int h=0;h<4;h++) v[h] = g_h[(size_t)r*512 + h*128 + t];
  __shared__ float rs[4][128], rq[4][128];
  #pragma unroll
  for (int h=0;h<4;h++){ rs[h][t]=v[h]; rq[h][t]=v[h]*v[h]; }
  __syncthreads();
  for (int sft=64; sft>=1; sft>>=1){
    if (t < sft){
      #pragma unroll
      for (int h=0;h<4;h++){ rs[h][t]+=rs[h][t+sft]; rq[h][t]+=rq[h][t+sft]; }
    }
    __syncthreads();
  }
  #pragma unroll
  for (int h=0;h<4;h++){
    float mean = rs[h][0]*(1.f/128.f);
    float var  = rq[h][0]*(1.f/128.f) - mean*mean;
    float hn = (v[h]-mean)*rsqrtf(var + 1e-5f);
    int e = h*128 + t;
    float hskip = hn + skip[e]*g_xc[(size_t)r*512 + e];
    g_hs[(size_t)r*512 + e] = hskip * g_zsil[(size_t)r*512 + e];
  }
}

// ---------------- launch ----------------
extern "C" void kernel_launch(void* const* d_in, const int* in_sizes, int n_in,
                              void* d_out, int out_size){
  const float* x      = (const float*)d_in[0];
  const float* W_up   = (const float*)d_in[1];
  const float* Wq     = (const float*)d_in[2];
  const float* Wk     = (const float*)d_in[3];
  const float* Wv     = (const float*)d_in[4];
  const float* conv_w = (const float*)d_in[5];
  const float* conv_b = (const float*)d_in[6];
  const float* Wi     = (const float*)d_in[7];
  const float* bi     = (const float*)d_in[8];
  const float* Wf     = (const float*)d_in[9];
  const float* bf     = (const float*)d_in[10];
  const float* skip   = (const float*)d_in[11];
  const float* W_down = (const float*)d_in[12];
  const float* b_down = (const float*)d_in[13];
  float* out = (float*)d_out;

  cudaFuncSetAttribute(k_attn, cudaFuncAttributeMaxDynamicSharedMemorySize, ATT_SMEM);
  cudaFuncSetAttribute(k_up,   cudaFuncAttributeMaxDynamicSharedMemorySize, GEMM_SMEM);
  cudaFuncSetAttribute(k_conv, cudaFuncAttributeMaxDynamicSharedMemorySize, GEMM_SMEM);
  cudaFuncSetAttribute(k_qkv,  cudaFuncAttributeMaxDynamicSharedMemorySize, GEMM_SMEM);
  cudaFuncSetAttribute(k_down, cudaFuncAttributeMaxDynamicSharedMemorySize, GEMM_SMEM);

  k_wt  <<<512, 512>>>(conv_w);
  k_up  <<<dim3(8,32), 256, GEMM_SMEM>>>(x, W_up);
  k_conv<<<dim3(4,32), 256, GEMM_SMEM>>>(conv_b);
  k_qkv <<<dim3(1,32,12), 256, GEMM_SMEM>>>(Wq, Wk, Wv);
  k_gates<<<4096,128>>>(Wi, bi, Wf, bf);
  k_scan<<<8,256>>>();
  k_attn<<<dim3(32,8),256, ATT_SMEM>>>();
  k_norm<<<4096,128>>>(skip);
  k_down<<<dim3(4,32),256, GEMM_SMEM>>>(W_down, b_down, out);
}

// round 16
// speedup vs baseline: 1.1682x; 1.1682x over previous
#include <cuda_runtime.h>
#include <cuda_bf16.h>
#include <math.h>

#define B_  2
#define S_  2048
#define E_  512
#define NH_ 4
#define DH_ 128
#define R_  (B_*S_)

// ------------------------- device scratch -------------------------
__device__ float g_xm  [R_*E_];
__device__ float g_zsil[R_*E_];
__device__ float g_xc  [R_*E_];
__device__ float g_q   [R_*E_];
__device__ float g_k   [R_*E_];
__device__ float g_v   [R_*E_];
__device__ float g_h   [R_*E_];
__device__ float g_hs  [R_*E_];
__device__ float g_Wt  [E_*4*E_];          // [o][tap*512+i]
// pre-split bf16 planes for attention: [row][head*64 + word], word = bf16x2 (dims 2w,2w+1)
__device__ unsigned g_qh[R_*256], g_ql[R_*256];
__device__ unsigned g_kh[R_*256], g_kl[R_*256];
__device__ unsigned g_vh[R_*256], g_vl[R_*256];
__device__ float g_ig  [B_*NH_*S_];
__device__ float g_fg  [B_*NH_*S_];
__device__ float g_dkey[B_*NH_*S_];
__device__ float g_mrow[B_*NH_*S_];
__device__ float g_mexp[B_*NH_*S_];

// ------------------------- helpers -------------------------
__device__ __forceinline__ void mma16(float c[4], const unsigned a[4], const unsigned b[2]){
  asm volatile("mma.sync.aligned.m16n8k16.row.col.f32.bf16.bf16.f32 "
    "{%0,%1,%2,%3}, {%4,%5,%6,%7}, {%8,%9}, {%0,%1,%2,%3};"
    : "+f"(c[0]),"+f"(c[1]),"+f"(c[2]),"+f"(c[3])
    : "r"(a[0]),"r"(a[1]),"r"(a[2]),"r"(a[3]), "r"(b[0]),"r"(b[1]));
}
__device__ __forceinline__ void ldm4(unsigned r[4], unsigned a){
  asm volatile("ldmatrix.sync.aligned.m8n8.x4.shared.b16 {%0,%1,%2,%3}, [%4];"
    : "=r"(r[0]),"=r"(r[1]),"=r"(r[2]),"=r"(r[3]) : "r"(a));
}
__device__ __forceinline__ void ldm4t(unsigned r[4], unsigned a){
  asm volatile("ldmatrix.sync.aligned.m8n8.x4.trans.shared.b16 {%0,%1,%2,%3}, [%4];"
    : "=r"(r[0]),"=r"(r[1]),"=r"(r[2]),"=r"(r[3]) : "r"(a));
}
__device__ __forceinline__ void cpa16(unsigned dst, const void* src){
  asm volatile("cp.async.cg.shared.global [%0], [%1], 16;" :: "r"(dst), "l"(src));
}
#define CP_COMMIT asm volatile("cp.async.commit_group;" ::: "memory")
#define CP_WAIT0  asm volatile("cp.async.wait_group 0;" ::: "memory")
__device__ __forceinline__ float silu(float x){ return x/(1.f+__expf(-x)); }
__device__ __forceinline__ unsigned pkb(__nv_bfloat16 lo, __nv_bfloat16 hi){
  return ((unsigned)__bfloat16_as_ushort(hi)<<16) | (unsigned)__bfloat16_as_ushort(lo);
}
__device__ __forceinline__ void spb4(unsigned hw[2], unsigned lw[2], float4 v){
  __nv_bfloat16 h0=__float2bfloat16_rn(v.x), h1=__float2bfloat16_rn(v.y),
                h2=__float2bfloat16_rn(v.z), h3=__float2bfloat16_rn(v.w);
  float l0=v.x-__bfloat162float(h0), l1=v.y-__bfloat162float(h1),
        l2=v.z-__bfloat162float(h2), l3=v.w-__bfloat162float(h3);
  hw[0]=pkb(h0,h1); hw[1]=pkb(h2,h3);
  lw[0]=pkb(__float2bfloat16_rn(l0),__float2bfloat16_rn(l1));
  lw[1]=pkb(__float2bfloat16_rn(l2),__float2bfloat16_rn(l3));
}
__device__ __forceinline__ void spb2(unsigned&hw, unsigned&lw, float a, float b){
  __nv_bfloat16 h0=__float2bfloat16_rn(a), h1=__float2bfloat16_rn(b);
  hw = pkb(h0,h1);
  lw = pkb(__float2bfloat16_rn(a-__bfloat162float(h0)),
           __float2bfloat16_rn(b-__bfloat162float(h1)));
}

// ---------------- conv weight repack: Wt[o][tap*512+i] ----------------
__global__ void k_wt(const float* __restrict__ conv_w){
  int o = blockIdx.x; int i = threadIdx.x;
  #pragma unroll
  for (int tap=0;tap<4;tap++)
    g_Wt[(size_t)o*2048 + tap*512 + i] = conv_w[((size_t)o*512+i)*4 + tap];
}

// ---------------- pipelined split-BF16 mma GEMM core (ldmatrix) ----------
#define WPR 12
#define TW  (128*WPR)
#define GST (4*TW)
#define GEMM_SMEM (2*GST*4)

__device__ __forceinline__ void mm_slice_bf(
    unsigned uAh, unsigned uAl, unsigned uBh, unsigned uBl,
    int wm, int wn, int lane, float acc[2][8][4])
{
  const int ar = ((lane>>3)&1)*8 + (lane&7);
  const int aw = (lane>>4)*4;
  const int br = (lane>>4)*8 + (lane&7);
  const int bw = ((lane>>3)&1)*4;
  unsigned ua[2][4], la[2][4];
  #pragma unroll
  for (int mt=0;mt<2;mt++){
    unsigned off = (unsigned)(((wm+mt*16+ar)*WPR + aw)*4);
    ldm4(ua[mt], uAh + off);
    ldm4(la[mt], uAl + off);
  }
  #pragma unroll
  for (int p=0;p<4;p++){
    unsigned off = (unsigned)(((wn + p*16 + br)*WPR + bw)*4);
    unsigned ub[4], lb[4];
    ldm4(ub, uBh + off);
    ldm4(lb, uBl + off);
    #pragma unroll
    for (int q=0;q<2;q++){
      unsigned ubq[2]={ub[2*q],ub[2*q+1]}, lbq[2]={lb[2*q],lb[2*q+1]};
      int nt = 2*p+q;
      #pragma unroll
      for (int mt=0;mt<2;mt++){
        mma16(acc[mt][nt], la[mt], ubq);
        mma16(acc[mt][nt], ua[mt], lbq);
        mma16(acc[mt][nt], ua[mt], ubq);
      }
    }
  }
}

__device__ __forceinline__ void mm_core_bf(
    const float* __restrict__ A, int lda,
    const float* __restrict__ W, int ldw, int K,
    unsigned* __restrict__ smw, float acc[2][8][4])
{
  const int tid=threadIdx.x, warp=tid>>5, lane=tid&31;
  const int wm=(warp>>1)*32, wn=(warp&1)*64;
  const int m0=tid>>2, m1=m0+64, c0=(tid&3)*4, w0=c0>>1;
  const unsigned ubase = (unsigned)__cvta_generic_to_shared(smw);
  float4 ra0 = *(const float4*)&A[(size_t)m0*lda + c0];
  float4 ra1 = *(const float4*)&A[(size_t)m1*lda + c0];
  float4 rb0 = *(const float4*)&W[(size_t)m0*ldw + c0];
  float4 rb1 = *(const float4*)&W[(size_t)m1*ldw + c0];
  int buf = 0;
  for (int k0=0;k0<K;k0+=16){
    unsigned* Ah = smw + buf*GST;
    unsigned* Al = Ah + TW;
    unsigned* Bh = Al + TW;
    unsigned* Bl = Bh + TW;
    unsigned hw[2], lw[2];
    spb4(hw,lw,ra0); Ah[m0*WPR+w0]=hw[0]; Ah[m0*WPR+w0+1]=hw[1]; Al[m0*WPR+w0]=lw[0]; Al[m0*WPR+w0+1]=lw[1];
    spb4(hw,lw,ra1); Ah[m1*WPR+w0]=hw[0]; Ah[m1*WPR+w0+1]=hw[1]; Al[m1*WPR+w0]=lw[0]; Al[m1*WPR+w0+1]=lw[1];
    spb4(hw,lw,rb0); Bh[m0*WPR+w0]=hw[0]; Bh[m0*WPR+w0+1]=hw[1]; Bl[m0*WPR+w0]=lw[0]; Bl[m0*WPR+w0+1]=lw[1];
    spb4(hw,lw,rb1); Bh[m1*WPR+w0]=hw[0]; Bh[m1*WPR+w0+1]=hw[1]; Bl[m1*WPR+w0]=lw[0]; Bl[m1*WPR+w0+1]=lw[1];
    __syncthreads();
    if (k0+16 < K){
      ra0 = *(const float4*)&A[(size_t)m0*lda + k0+16 + c0];
      ra1 = *(const float4*)&A[(size_t)m1*lda + k0+16 + c0];
      rb0 = *(const float4*)&W[(size_t)m0*ldw + k0+16 + c0];
      rb1 = *(const float4*)&W[(size_t)m1*ldw + k0+16 + c0];
    }
    unsigned ust = ubase + (unsigned)(buf*GST*4);
    mm_slice_bf(ust, ust+TW*4, ust+2*TW*4, ust+3*TW*4, wm, wn, lane, acc);
    buf ^= 1;
  }
}

#define EPI_COORDS \
  const int tid=threadIdx.x, warp=tid>>5, lane=tid&31, gid=lane>>2, tig=lane&3; \
  const int wm=(warp>>1)*32, wn=(warp&1)*64; (void)wm; (void)tid;

// ---------------- up projection ----------------
__global__ __launch_bounds__(256,2) void k_up(const float* __restrict__ X,
                                              const float* __restrict__ Wup){
  extern __shared__ unsigned smw[];
  int bm = blockIdx.y*128, bn = blockIdx.x*128;
  float acc[2][8][4];
  #pragma unroll
  for(int i=0;i<2;i++)for(int j=0;j<8;j++)for(int e=0;e<4;e++)acc[i][j][e]=0;
  mm_core_bf(X+(size_t)bm*512, 512, Wup+(size_t)bn*512, 512, 512, smw, acc);
  EPI_COORDS;
  bool is_z = (bn >= 512);
  #pragma unroll
  for (int mt=0;mt<2;mt++){
    #pragma unroll
    for (int nt=0;nt<8;nt++){
      int row = bm+wm+mt*16+gid;
      int col = bn+wn+nt*8+tig*2;
      float* c = acc[mt][nt];
      if (!is_z){
        *(float2*)&g_xm[(size_t)row*512+col]     = make_float2(c[0],c[1]);
        *(float2*)&g_xm[(size_t)(row+8)*512+col] = make_float2(c[2],c[3]);
      } else {
        int cz = col-512;
        *(float2*)&g_zsil[(size_t)row*512+cz]     = make_float2(silu(c[0]),silu(c[1]));
        *(float2*)&g_zsil[(size_t)(row+8)*512+cz] = make_float2(silu(c[2]),silu(c[3]));
      }
    }
  }
}

// ---------------- causal conv1d as shifted GEMM + silu ----------------
__global__ __launch_bounds__(256,2) void k_conv(const float* __restrict__ convb){
  extern __shared__ unsigned smw[];
  int bm = blockIdx.y*128, bn = blockIdx.x*128;
  const int tid=threadIdx.x, warp=tid>>5, lane=tid&31, gid=lane>>2, tig=lane&3;
  const int wm=(warp>>1)*32, wn=(warp&1)*64;
  const int m0=tid>>2, m1=m0+64, c0=(tid&3)*4, w0=c0>>1;
  const int s0 = (bm+m0)&(S_-1), s1 = (bm+m1)&(S_-1);
  const unsigned ubase = (unsigned)__cvta_generic_to_shared(smw);
  float acc[2][8][4];
  #pragma unroll
  for(int i=0;i<2;i++)for(int j=0;j<8;j++)for(int e=0;e<4;e++)acc[i][j][e]=0;
  const float* W = g_Wt + (size_t)bn*2048;
  float4 ra0 = (s0-3>=0) ? *(const float4*)&g_xm[(size_t)(bm+m0-3)*512 + c0] : make_float4(0,0,0,0);
  float4 ra1 = (s1-3>=0) ? *(const float4*)&g_xm[(size_t)(bm+m1-3)*512 + c0] : make_float4(0,0,0,0);
  float4 rb0 = *(const float4*)&W[(size_t)m0*2048 + c0];
  float4 rb1 = *(const float4*)&W[(size_t)m1*2048 + c0];
  int buf = 0;
  for (int k0=0;k0<2048;k0+=16){
    unsigned* Ah = smw + buf*GST;
    unsigned* Al = Ah + TW;
    unsigned* Bh = Al + TW;
    unsigned* Bl = Bh + TW;
    unsigned hw[2], lw[2];
    spb4(hw,lw,ra0); Ah[m0*WPR+w0]=hw[0]; Ah[m0*WPR+w0+1]=hw[1]; Al[m0*WPR+w0]=lw[0]; Al[m0*WPR+w0+1]=lw[1];
    spb4(hw,lw,ra1); Ah[m1*WPR+w0]=hw[0]; Ah[m1*WPR+w0+1]=hw[1]; Al[m1*WPR+w0]=lw[0]; Al[m1*WPR+w0+1]=lw[1];
    spb4(hw,lw,rb0); Bh[m0*WPR+w0]=hw[0]; Bh[m0*WPR+w0+1]=hw[1]; Bl[m0*WPR+w0]=lw[0]; Bl[m0*WPR+w0+1]=lw[1];
    spb4(hw,lw,rb1); Bh[m1*WPR+w0]=hw[0]; Bh[m1*WPR+w0+1]=hw[1]; Bl[m1*WPR+w0]=lw[0]; Bl[m1*WPR+w0+1]=lw[1];
    __syncthreads();
    int kn = k0+16;
    if (kn < 2048){
      int tap = kn>>9, i0 = kn&511;
      ra0 = (s0+tap-3>=0) ? *(const float4*)&g_xm[(size_t)(bm+m0+tap-3)*512 + i0 + c0]
                          : make_float4(0,0,0,0);
      ra1 = (s1+tap-3>=0) ? *(const float4*)&g_xm[(size_t)(bm+m1+tap-3)*512 + i0 + c0]
                          : make_float4(0,0,0,0);
      rb0 = *(const float4*)&W[(size_t)m0*2048 + kn + c0];
      rb1 = *(const float4*)&W[(size_t)m1*2048 + kn + c0];
    }
    unsigned ust = ubase + (unsigned)(buf*GST*4);
    mm_slice_bf(ust, ust+TW*4, ust+2*TW*4, ust+3*TW*4, wm, wn, lane, acc);
    buf ^= 1;
  }
  #pragma unroll
  for (int mt=0;mt<2;mt++){
    #pragma unroll
    for (int nt=0;nt<8;nt++){
      int row = bm+wm+mt*16+gid;
      int col = bn+wn+nt*8+tig*2;
      float b0 = convb[col], b1 = convb[col+1];
      float* c = acc[mt][nt];
      *(float2*)&g_xc[(size_t)row*512+col]     = make_float2(silu(c[0]+b0),silu(c[1]+b1));
      *(float2*)&g_xc[(size_t)(row+8)*512+col] = make_float2(silu(c[2]+b0),silu(c[3]+b1));
    }
  }
}

// ---------------- headwise q/k/v (+ pre-split bf16 planes) ----------------
__global__ __launch_bounds__(256,2) void k_qkv(const float* __restrict__ Wq,
                                               const float* __restrict__ Wk,
                                               const float* __restrict__ Wv){
  extern __shared__ unsigned smw[];
  int zz = blockIdx.z; int op = zz>>2; int h = zz&3;
  const float* A  = (op==2 ? g_xm : g_xc) + h*128;
  const float* Wp = (op==0 ? Wq : (op==1 ? Wk : Wv)) + (size_t)h*128*128;
  float* Cp = (op==0 ? g_q : (op==1 ? g_k : g_v)) + h*128;
  unsigned* Ph = (op==0 ? g_qh : (op==1 ? g_kh : g_vh));
  unsigned* Pl = (op==0 ? g_ql : (op==1 ? g_kl : g_vl));
  int bm = blockIdx.y*128;
  float acc[2][8][4];
  #pragma unroll
  for(int i=0;i<2;i++)for(int j=0;j<8;j++)for(int e=0;e<4;e++)acc[i][j][e]=0;
  mm_core_bf(A+(size_t)bm*512, 512, Wp, 128, 128, smw, acc);
  EPI_COORDS;
  #pragma unroll
  for (int mt=0;mt<2;mt++){
    #pragma unroll
    for (int nt=0;nt<8;nt++){
      int row = bm+wm+mt*16+gid;
      int col = wn+nt*8+tig*2;           // 0..126 within head
      int cw  = col>>1;                  // word index 0..63
      float* c = acc[mt][nt];
      *(float2*)&Cp[(size_t)row*512+col]     = make_float2(c[0],c[1]);
      *(float2*)&Cp[(size_t)(row+8)*512+col] = make_float2(c[2],c[3]);
      unsigned hw, lw;
      spb2(hw,lw,c[0],c[1]);
      Ph[(size_t)row*256 + h*64 + cw] = hw;
      Pl[(size_t)row*256 + h*64 + cw] = lw;
      spb2(hw,lw,c[2],c[3]);
      Ph[(size_t)(row+8)*256 + h*64 + cw] = hw;
      Pl[(size_t)(row+8)*256 + h*64 + cw] = lw;
    }
  }
}

// ---------------- down projection + bias ----------------
__global__ __launch_bounds__(256,2) void k_down(const float* __restrict__ Wd,
                                                const float* __restrict__ bd,
                                                float* __restrict__ out){
  extern __shared__ unsigned smw[];
  int bm = blockIdx.y*128, bn = blockIdx.x*128;
  float acc[2][8][4];
  #pragma unroll
  for(int i=0;i<2;i++)for(int j=0;j<8;j++)for(int e=0;e<4;e++)acc[i][j][e]=0;
  mm_core_bf(g_hs+(size_t)bm*512, 512, Wd+(size_t)bn*512, 512, 512, smw, acc);
  EPI_COORDS;
  #pragma unroll
  for (int mt=0;mt<2;mt++){
    #pragma unroll
    for (int nt=0;nt<8;nt++){
      int row = bm+wm+mt*16+gid;
      int col = bn+wn+nt*8+tig*2;
      float b0 = bd[col], b1 = bd[col+1];
      float* c = acc[mt][nt];
      *(float2*)&out[(size_t)row*512+col]     = make_float2(c[0]+b0,c[1]+b1);
      *(float2*)&out[(size_t)(row+8)*512+col] = make_float2(c[2]+b0,c[3]+b1);
    }
  }
}

// ---------------- gate projections ----------------
__global__ void k_gates(const float* __restrict__ Wi, const float* __restrict__ bi,
                        const float* __restrict__ Wf, const float* __restrict__ bf){
  int r = blockIdx.x; int tid = threadIdx.x;
  float pi[4]={0,0,0,0}, pf[4]={0,0,0,0};
  const float* qr = g_q + (size_t)r*512;
  const float* kr = g_k + (size_t)r*512;
  const float* vr = g_v + (size_t)r*512;
  for (int e=tid; e<512; e+=128){
    float a=qr[e], c=kr[e], d=vr[e];
    #pragma unroll
    for (int h=0;h<4;h++){
      const float* wih = Wi + h*1536; const float* wfh = Wf + h*1536;
      pi[h] += a*wih[e] + c*wih[512+e] + d*wih[1024+e];
      pf[h] += a*wfh[e] + c*wfh[512+e] + d*wfh[1024+e];
    }
  }
  __shared__ float red[8][128];
  #pragma unroll
  for (int h=0;h<4;h++){ red[h][tid]=pi[h]; red[4+h][tid]=pf[h]; }
  __syncthreads();
  for (int sft=64; sft>=1; sft>>=1){
    if (tid < sft){
      #pragma unroll
      for (int a=0;a<8;a++) red[a][tid]+=red[a][tid+sft];
    }
    __syncthreads();
  }
  if (tid < 4){
    int b = r>>11, s = r&2047;
    g_ig[((size_t)b*4+tid)*2048 + s] = red[tid][0]   + bi[tid];
    g_fg[((size_t)b*4+tid)*2048 + s] = red[4+tid][0] + bf[tid];
  }
}

// ---------------- per-(b,h) scan ----------------
__global__ void k_scan(){
  int bh = blockIdx.x; int t = threadIdx.x;
  const float* fg = g_fg + (size_t)bh*2048;
  const float* ig = g_ig + (size_t)bh*2048;
  double lcum[8]; double run = 0.0;
  #pragma unroll
  for (int u=0;u<8;u++){
    double x = (double)fg[t*8+u];
    double ls = (x < 0.0) ? (x - log1p(exp(x))) : (-log1p(exp(-x)));
    run += ls; lcum[u] = run;
  }
  __shared__ double sh[256];
  sh[t] = run; __syncthreads();
  for (int off=1; off<256; off<<=1){
    double cur = sh[t]; double oth = (t>=off)? sh[t-off] : 0.0;
    __syncthreads(); sh[t] = cur + oth; __syncthreads();
  }
  double base = (t>0)? sh[t-1] : 0.0;
  double dv[8], lf[8]; double runm = -1e300;
  #pragma unroll
  for (int u=0;u<8;u++){
    double lfc = base + lcum[u];
    lf[u] = lfc; dv[u] = (double)ig[t*8+u] - lfc;
    if (dv[u] > runm) runm = dv[u];
  }
  __syncthreads();
  sh[t] = runm; __syncthreads();
  for (int off=1; off<256; off<<=1){
    double cur = sh[t]; double oth = (t>=off)? sh[t-off] : -1e300;
    __syncthreads(); sh[t] = (cur>oth)?cur:oth; __syncthreads();
  }
  double basem = (t>0)? sh[t-1] : -1e300;
  double rm = basem;
  #pragma unroll
  for (int u=0;u<8;u++){
    if (dv[u] > rm) rm = dv[u];
    int j = bh*2048 + t*8 + u;
    g_dkey[j] = (float)dv[u];
    g_mrow[j] = (float)rm;
    g_mexp[j] = (float)exp(-(lf[u] + rm));
  }
}

// ---------------- split-BF16 flash attention (cp.async + ldmatrix) -------
#define WQROW 68
#define WSROW 36
#define AQH 0
#define AQL (64*WQROW)
#define AKH (2*64*WQROW)
#define AKL (3*64*WQROW)
#define ASH (4*64*WQROW)
#define ASL (ASH + 64*WSROW)
#define ADK (ASL + 64*WSROW)
#define ARED (ADK + 64)
#define ASINV (ARED + 128)
#define ATT_WORDS (ASINV + 64)
#define ATT_SMEM (ATT_WORDS*4)

__global__ __launch_bounds__(256,2) void k_attn(){
  extern __shared__ unsigned smu[];
  unsigned* SSH = smu + ASH;
  unsigned* SSL = smu + ASL;
  float* dks = (float*)(smu + ADK);
  float* red = (float*)(smu + ARED);
  float* sinv= (float*)(smu + ASINV);
  const unsigned ub0 = (unsigned)__cvta_generic_to_shared(smu);
  const unsigned uQH = ub0 + AQH*4, uQL = ub0 + AQL*4;
  const unsigned uKH = ub0 + AKH*4, uKL = ub0 + AKL*4;   // V aliases K buffers
  const unsigned uSSH= ub0 + ASH*4, uSSL= ub0 + ASL*4;

  int bh = blockIdx.y; int b = bh>>2, h = bh&3;
  int it = (int)gridDim.x - 1 - (int)blockIdx.x;
  int i0 = it*64;
  const int tid=threadIdx.x, warp=tid>>5, lane=tid&31, gid=lane>>2, tig=lane&3;
  const int wr=warp>>1, wc=warp&1;
  const int qm = wr*16;
  const float scale = 0.08838834764831845f;
  // tile copy coords: 2048 16B-chunks (plane, row, chunk)
  // ldmatrix coords
  const int ar = ((lane>>3)&1)*8 + (lane&7);
  const int aw = (lane>>4)*4;
  const int br = (lane>>4)*8 + (lane&7);
  const int bw = ((lane>>3)&1)*4;
  const int tr = (lane&7) + ((lane>>3)&1)*8;   // trans: j-row
  const int tc = (lane>>4)*4;                  // trans: d-word offset

  // async-load Q tile (once)
  {
    size_t rb = (size_t)(b*2048 + i0);
    #pragma unroll
    for (int u=0;u<8;u++){
      int ch = tid + u*256;
      int plane = ch>>10, r = (ch>>4)&63, c = ch&15;
      const unsigned* src = (plane? g_ql : g_qh) + (rb+r)*256 + h*64 + c*4;
      unsigned dst = ub0 + (unsigned)(((plane? AQL:AQH) + r*WQROW + c*4)*4);
      cpa16(dst, src);
    }
    CP_COMMIT;
  }
  float mr0 = g_mrow[bh*2048 + i0 + qm + gid];
  float mr1 = g_mrow[bh*2048 + i0 + qm + gid + 8];

  float oacc[8][4];
  #pragma unroll
  for (int nt=0;nt<8;nt++){oacc[nt][0]=0;oacc[nt][1]=0;oacc[nt][2]=0;oacc[nt][3]=0;}
  float psum0 = 0.f, psum1 = 0.f;

  for (int j0 = 0; j0 <= i0; j0 += 64){
    __syncthreads();                          // prev SV done; K/V buffers free
    {
      size_t rb = (size_t)(b*2048 + j0);
      #pragma unroll
      for (int u=0;u<8;u++){
        int ch = tid + u*256;
        int plane = ch>>10, r = (ch>>4)&63, c = ch&15;
        const unsigned* src = (plane? g_kl : g_kh) + (rb+r)*256 + h*64 + c*4;
        unsigned dst = ub0 + (unsigned)(((plane? AKL:AKH) + r*WQROW + c*4)*4);
        cpa16(dst, src);
      }
    }
    if (tid < 64) dks[tid] = g_dkey[bh*2048 + j0 + tid];
    CP_COMMIT; CP_WAIT0;
    __syncthreads();

    // QK^T: rows qm..qm+15, key cols wc*32..+31
    float sacc[4][4];
    #pragma unroll
    for (int nt=0;nt<4;nt++){sacc[nt][0]=0;sacc[nt][1]=0;sacc[nt][2]=0;sacc[nt][3]=0;}
    #pragma unroll
    for (int kk=0;kk<128;kk+=16){
      int wb = kk>>1;
      unsigned offA = (unsigned)(((qm+ar)*WQROW + wb + aw)*4);
      unsigned ua[4], la[4];
      ldm4(ua, uQH + offA);
      ldm4(la, uQL + offA);
      #pragma unroll
      for (int p=0;p<2;p++){
        unsigned offB = (unsigned)(((wc*32 + p*16 + br)*WQROW + wb + bw)*4);
        unsigned kb2[4], klb[4];
        ldm4(kb2, uKH + offB);
        ldm4(klb, uKL + offB);
        #pragma unroll
        for (int q=0;q<2;q++){
          unsigned ubq[2]={kb2[2*q],kb2[2*q+1]}, lbq[2]={klb[2*q],klb[2*q+1]};
          int nt = 2*p+q;
          mma16(sacc[nt], la, ubq);
          mma16(sacc[nt], ua, lbq);
          mma16(sacc[nt], ua, ubq);
        }
      }
    }
    bool diag = (j0 == i0);
    #pragma unroll
    for (int nt=0;nt<4;nt++){
      int jl = wc*32+nt*8+tig*2;
      float d0 = dks[jl], d1 = dks[jl+1];
      int il0 = qm+gid, il1 = il0+8;
      float s00 = sacc[nt][0]*scale*__expf(d0 - mr0);
      float s01 = sacc[nt][1]*scale*__expf(d1 - mr0);
      float s10 = sacc[nt][2]*scale*__expf(d0 - mr1);
      float s11 = sacc[nt][3]*scale*__expf(d1 - mr1);
      if (diag){
        if (jl   > il0) s00 = 0.f;
        if (jl+1 > il0) s01 = 0.f;
        if (jl   > il1) s10 = 0.f;
        if (jl+1 > il1) s11 = 0.f;
      }
      psum0 += s00 + s01;
      psum1 += s10 + s11;
      int jw = jl>>1;
      unsigned hw, lw;
      spb2(hw,lw,s00,s01); SSH[il0*WSROW + jw]=hw; SSL[il0*WSROW + jw]=lw;
      spb2(hw,lw,s10,s11); SSH[il1*WSROW + jw]=hw; SSL[il1*WSROW + jw]=lw;
    }
    __syncthreads();                 // K consumed, S visible

    // async-load V into the K buffers (row-major [j][d-words])
    {
      size_t rb = (size_t)(b*2048 + j0);
      #pragma unroll
      for (int u=0;u<8;u++){
        int ch = tid + u*256;
        int plane = ch>>10, r = (ch>>4)&63, c = ch&15;
        const unsigned* src = (plane? g_vl : g_vh) + (rb+r)*256 + h*64 + c*4;
        unsigned dst = ub0 + (unsigned)(((plane? AKL:AKH) + r*WQROW + c*4)*4);
        cpa16(dst, src);
      }
      CP_COMMIT; CP_WAIT0;
    }
    __syncthreads();

    // S @ V: rows qm..qm+15, d cols wc*64..+63 ; B via ldmatrix.trans on V
    #pragma unroll
    for (int kk=0;kk<64;kk+=16){
      unsigned offA = (unsigned)(((qm+ar)*WSROW + (kk>>1) + aw)*4);
      unsigned ua[4], la[4];
      ldm4(ua, uSSH + offA);
      ldm4(la, uSSL + offA);
      #pragma unroll
      for (int p=0;p<4;p++){
        int colw = wc*32 + p*8 + tc;
        unsigned offB = (unsigned)(((kk + tr)*WQROW + colw)*4);
        unsigned vb2[4], vlb[4];
        ldm4t(vb2, uKH + offB);
        ldm4t(vlb, uKL + offB);
        #pragma unroll
        for (int q=0;q<2;q++){
          unsigned ubq[2]={vb2[2*q],vb2[2*q+1]}, lbq[2]={vlb[2*q],vlb[2*q+1]};
          int nt = 2*p+q;
          mma16(oacc[nt], la, ubq);
          mma16(oacc[nt], ua, lbq);
          mma16(oacc[nt], ua, ubq);
        }
      }
    }
  }

  psum0 += __shfl_xor_sync(0xffffffffu, psum0, 1);
  psum0 += __shfl_xor_sync(0xffffffffu, psum0, 2);
  psum1 += __shfl_xor_sync(0xffffffffu, psum1, 1);
  psum1 += __shfl_xor_sync(0xffffffffu, psum1, 2);
  if (tig == 0){
    red[(qm+gid)*2   + wc] = psum0;
    red[(qm+gid+8)*2 + wc] = psum1;
  }
  __syncthreads();
  if (tid < 64){
    float s2 = red[tid*2] + red[tid*2+1];
    float nrm = fmaxf(fabsf(s2), g_mexp[bh*2048 + i0 + tid]);
    sinv[tid] = 1.f/(nrm + 1e-6f);
  }
  __syncthreads();

  float iv0 = sinv[qm+gid], iv1 = sinv[qm+gid+8];
  float* obase = g_h + ((size_t)(b*2048 + i0))*512 + h*128;
  #pragma unroll
  for (int nt=0;nt<8;nt++){
    int col = wc*64+nt*8+tig*2;
    *(float2*)&obase[(size_t)(qm+gid)*512 + col] =
      make_float2(oacc[nt][0]*iv0, oacc[nt][1]*iv0);
    *(float2*)&obase[(size_t)(qm+gid+8)*512 + col] =
      make_float2(oacc[nt][2]*iv1, oacc[nt][3]*iv1);
  }
}

// ---------------- groupnorm + skip + z-gate ----------------
__global__ void k_norm(const float* __restrict__ skip){
  int r = blockIdx.x; int t = threadIdx.x;
  float v[4];
  #pragma unroll
  for (int h=0;h<4;h++) v[h] = g_h[(size_t)r*512 + h*128 + t];
  __shared__ float rs[4][128], rq[4][128];
  #pragma unroll
  for (int h=0;h<4;h++){ rs[h][t]=v[h]; rq[h][t]=v[h]*v[h]; }
  __syncthreads();
  for (int sft=64; sft>=1; sft>>=1){
    if (t < sft){
      #pragma unroll
      for (int h=0;h<4;h++){ rs[h][t]+=rs[h][t+sft]; rq[h][t]+=rq[h][t+sft]; }
    }
    __syncthreads();
  }
  #pragma unroll
  for (int h=0;h<4;h++){
    float mean = rs[h][0]*(1.f/128.f);
    float var  = rq[h][0]*(1.f/128.f) - mean*mean;
    float hn = (v[h]-mean)*rsqrtf(var + 1e-5f);
    int e = h*128 + t;
    float hskip = hn + skip[e]*g_xc[(size_t)r*512 + e];
    g_hs[(size_t)r*512 + e] = hskip * g_zsil[(size_t)r*512 + e];
  }
}

// ---------------- launch ----------------
extern "C" void kernel_launch(void* const* d_in, const int* in_sizes, int n_in,
                              void* d_out, int out_size){
  const float* x      = (const float*)d_in[0];
  const float* W_up   = (const float*)d_in[1];
  const float* Wq     = (const float*)d_in[2];
  const float* Wk     = (const float*)d_in[3];
  const float* Wv     = (const float*)d_in[4];
  const float* conv_w = (const float*)d_in[5];
  const float* conv_b = (const float*)d_in[6];
  const float* Wi     = (const float*)d_in[7];
  const float* bi     = (const float*)d_in[8];
  const float* Wf     = (const float*)d_in[9];
  const float* bf     = (const float*)d_in[10];
  const float* skip   = (const float*)d_in[11];
  const float* W_down = (const float*)d_in[12];
  const float* b_down = (const float*)d_in[13];
  float* out = (float*)d_out;

  cudaFuncSetAttribute(k_attn, cudaFuncAttributeMaxDynamicSharedMemorySize, ATT_SMEM);
  cudaFuncSetAttribute(k_up,   cudaFuncAttributeMaxDynamicSharedMemorySize, GEMM_SMEM);
  cudaFuncSetAttribute(k_conv, cudaFuncAttributeMaxDynamicSharedMemorySize, GEMM_SMEM);
  cudaFuncSetAttribute(k_qkv,  cudaFuncAttributeMaxDynamicSharedMemorySize, GEMM_SMEM);
  cudaFuncSetAttribute(k_down, cudaFuncAttributeMaxDynamicSharedMemorySize, GEMM_SMEM);

  k_wt  <<<512, 512>>>(conv_w);
  k_up  <<<dim3(8,32), 256, GEMM_SMEM>>>(x, W_up);
  k_conv<<<dim3(4,32), 256, GEMM_SMEM>>>(conv_b);
  k_qkv <<<dim3(1,32,12), 256, GEMM_SMEM>>>(Wq, Wk, Wv);
  k_gates<<<4096,128>>>(Wi, bi, Wf, bf);
  k_scan<<<8,256>>>();
  k_attn<<<dim3(32,8),256, ATT_SMEM>>>();
  k_norm<<<4096,128>>>(skip);
  k_down<<<dim3(4,32),256, GEMM_SMEM>>>(W_down, b_down, out);
}